// round 15
// baseline (speedup 1.0000x reference)
#include <cuda_runtime.h>
#include <math.h>

// ---------------- problem constants ----------------
#define BB   32
#define TT   4096
#define AD   128
#define SS   100
#define BDM  10
#define HH   50
#define DD   30
#define CH   64            // chunk = 64 timesteps (k_dp1 pipeline)
#define NCH  (TT / CH)     // 64 chunks
#define NQ   25            // S/4 float4 "quads"
#define TROW 65            // padded tile row (float4) in k_dp1
#define GR   32            // group = 32 steps (bit granularity)
#define NGRP (TT / GR)     // 128 groups
#define BTROW 132          // bts words per group (100 used, padded)
#define GPW  8             // groups per CTA in k_dp2
#define ZCH  1024          // z chunk (timesteps) in k_final segsum
#define ZPAD 11            // padded z row (floats) in k_final stage
#define FULLM 0xffffffffu

// ---------------- global scratch ----------------
__device__ __align__(16) float4 g_simsT[(size_t)BB * NQ * TT];        // [b][q][t]
__device__ __align__(16) float  g_z[(size_t)BB * TT * BDM];
__device__ __align__(16) float  g_bnd[(size_t)BB * NGRP * SS];        // boundary vectors
__device__ __align__(16) unsigned int g_bts[(size_t)BB * NGRP * BTROW];

// =====================================================================
// Kernel 1: z = mlp(x); sims stored quad-transposed [b][q][t]
// =====================================================================
__global__ void k_project(const float* __restrict__ x, const float* __restrict__ c,
                          const float* __restrict__ w1, const float* __restrict__ b1,
                          const float* __restrict__ w2, const float* __restrict__ b2,
                          const float* __restrict__ w3, const float* __restrict__ b3)
{
    __shared__ float w1s[BDM * AD];
    __shared__ float cs[BDM * SS];
    __shared__ float w2s[BDM * BDM], w3s[BDM * BDM];
    __shared__ float b1s[BDM], b2s[BDM], b3s[BDM];

    int tid = threadIdx.x;
    for (int i = tid; i < BDM * AD; i += 256) w1s[i] = w1[i];
    for (int i = tid; i < BDM * SS; i += 256) cs[i] = c[i];
    if (tid < BDM * BDM) { w2s[tid] = w2[tid]; w3s[tid] = w3[tid]; }
    if (tid < BDM) { b1s[tid] = b1[tid]; b2s[tid] = b2[tid]; b3s[tid] = b3[tid]; }
    __syncthreads();

    int gtid = blockIdx.x * 256 + tid;         // b*T + t
    int b = gtid >> 12;
    int t = gtid & (TT - 1);
    const float4* xr = (const float4*)(x + (size_t)gtid * AD);

    float z1[BDM];
#pragma unroll
    for (int d = 0; d < BDM; d++) z1[d] = b1s[d];

#pragma unroll 8
    for (int kk = 0; kk < AD / 4; ++kk) {
        float4 xv = xr[kk];
#pragma unroll
        for (int d = 0; d < BDM; d++) {
            float4 wv = ((const float4*)w1s)[d * (AD / 4) + kk];
            z1[d] += xv.x * wv.x + xv.y * wv.y + xv.z * wv.z + xv.w * wv.w;
        }
    }
#pragma unroll
    for (int d = 0; d < BDM; d++) z1[d] = fmaxf(z1[d], 0.0f);

    float z2[BDM];
#pragma unroll
    for (int d = 0; d < BDM; d++) {
        float a = b2s[d];
#pragma unroll
        for (int e = 0; e < BDM; e++) a += z1[e] * w2s[d * BDM + e];
        z2[d] = fmaxf(a, 0.0f);
    }
    float z3[BDM];
#pragma unroll
    for (int d = 0; d < BDM; d++) {
        float a = b3s[d];
#pragma unroll
        for (int e = 0; e < BDM; e++) a += z2[e] * w3s[d * BDM + e];
        z3[d] = a;
    }

    float* zo = g_z + (size_t)gtid * BDM;
#pragma unroll
    for (int d = 0; d < BDM; d++) zo[d] = z3[d];

#pragma unroll
    for (int q = 0; q < NQ; ++q) {
        float4 a = make_float4(0.f, 0.f, 0.f, 0.f);
#pragma unroll
        for (int d = 0; d < BDM; d++) {
            float zv = z3[d];
            float4 cv = ((const float4*)cs)[d * NQ + q];
            a.x += zv * cv.x; a.y += zv * cv.y;
            a.z += zv * cv.z; a.w += zv * cv.w;
        }
        g_simsT[((size_t)b * NQ + q) * TT + t] = a;   // coalesced over t
    }
}

// =====================================================================
// helpers
// =====================================================================
__device__ __forceinline__ float sigm(float v) { return 1.0f / (1.0f + __expf(-v)); }

__device__ __forceinline__ float tanhfast(float v)
{
    float vc = fminf(fmaxf(v, -15.0f), 15.0f);
    float e = __expf(2.0f * vc);
    return 1.0f - 2.0f / (e + 1.0f);
}

__device__ __forceinline__ unsigned smem_u32(const void* p)
{
    return (unsigned)__cvta_generic_to_shared(p);
}

// =====================================================================
// Kernel 2a (k_dp1): slim forward DP (NO bits), stores boundary vectors
// every 32 steps. warp0 consumer, warps1-7 cp.async producers.
// =====================================================================
struct SmemD {
    float4 tile[2][NQ * TROW];     // 52,000 B
};

__device__ __forceinline__ void copy_chunk_async(SmemD* sm, int b, int p, int cn)
{
    if (p < 200) {
        float4* dst = sm->tile[cn & 1];
        const float4* src = g_simsT + (size_t)b * NQ * TT + (size_t)cn * CH;
#pragma unroll
        for (int k = 0; k < 8; k++) {
            int i = p + k * 200;
            int q = i >> 6;
            int r = i & 63;
            unsigned d = smem_u32(dst + q * TROW + r);
            const float4* g = src + (size_t)q * TT + r;
            asm volatile("cp.async.cg.shared.global [%0], [%1], 16;"
                         :: "r"(d), "l"(g) : "memory");
        }
        asm volatile("cp.async.commit_group;" ::: "memory");
        asm volatile("cp.async.wait_group 0;" ::: "memory");
    }
}

#define DPSLIM(sv) do {                                                          \
    float n3 = fmaxf(st2, st3) + (sv).w;                                         \
    float nsh = __shfl_up_sync(FULLM, n3, 1);                                    \
    float left = (lane == 0) ? 0.0f : left_next;                                 \
    float n1 = fmaxf(st0, st1) + (sv).y;                                         \
    float n2 = fmaxf(st1, st2) + (sv).z;                                         \
    float n0 = fmaxf(left, st0) + (sv).x;                                        \
    st0 = n0; st1 = n1; st2 = n2; st3 = n3; left_next = nsh; } while (0)

__global__ void __launch_bounds__(256, 1)
k_dp1()
{
    extern __shared__ unsigned char smraw[];
    SmemD* sm = reinterpret_cast<SmemD*>(smraw);

    const int tid = threadIdx.x;
    const int b = blockIdx.x;
    const int lane = tid & 31;

    if (tid >= 32) copy_chunk_async(sm, b, tid - 32, 0);
    __syncthreads();

    const int qln = lane < NQ ? lane : NQ - 1;
    float st0 = 0.f, st1 = 0.f, st2 = 0.f, st3 = 0.f, left_next = 0.f;

    for (int ci = 0; ci < NCH; ++ci) {
        if (tid < 32) {
            const float4* tb = sm->tile[ci & 1] + qln * TROW;
            if (ci == 0) {
                {
                    float4 sv = tb[0];
                    st0 = sv.x; st1 = sv.y; st2 = sv.z; st3 = sv.w;
                    left_next = __shfl_up_sync(FULLM, st3, 1);
                }
#pragma unroll
                for (int u = 1; u < 32; ++u) DPSLIM(tb[u]);
                if (lane < NQ)
                    *(float4*)&g_bnd[((size_t)b * NGRP + 1) * SS + 4 * lane] =
                        make_float4(st0, st1, st2, st3);
#pragma unroll
                for (int u = 32; u < 64; ++u) DPSLIM(tb[u]);
                if (lane < NQ)
                    *(float4*)&g_bnd[((size_t)b * NGRP + 2) * SS + 4 * lane] =
                        make_float4(st0, st1, st2, st3);
            } else {
#pragma unroll 1
                for (int g2 = 0; g2 < 2; ++g2) {
                    const float4* tg = tb + g2 * 32;
#pragma unroll
                    for (int u = 0; u < 32; ++u) DPSLIM(tg[u]);
                    int g = 2 * ci + g2 + 1;
                    if (g < NGRP && lane < NQ)
                        *(float4*)&g_bnd[((size_t)b * NGRP + g) * SS + 4 * lane] =
                            make_float4(st0, st1, st2, st3);
                }
            }
        } else {
            if (ci + 1 < NCH) copy_chunk_async(sm, b, tid - 32, ci + 1);
        }
        __syncthreads();
    }
}

// =====================================================================
// Kernel 2b (k_dp2): parallel bit recompute (exact boundary restart).
// =====================================================================
#define DPSTEP3(sv, U) do {                                                      \
    float n3 = fmaxf(st2, st3) + (sv).w;                                         \
    float nsh = __shfl_up_sync(FULLM, n3, 1);                                    \
    float left = (lane == 0) ? 0.0f : left_next;                                 \
    float d1 = st1 - st0;                                                        \
    float d2 = st2 - st1;                                                        \
    float d3 = st3 - st2;                                                        \
    float n1 = fmaxf(st0, st1) + (sv).y;                                         \
    float n2 = fmaxf(st1, st2) + (sv).z;                                         \
    acc1 |= (__float_as_uint(d1) >> (U)) & (1u << (31 - (U)));                   \
    acc2 |= (__float_as_uint(d2) >> (U)) & (1u << (31 - (U)));                   \
    acc3 |= (__float_as_uint(d3) >> (U)) & (1u << (31 - (U)));                   \
    float d0 = st0 - left;                                                       \
    float n0 = fmaxf(left, st0) + (sv).x;                                        \
    acc0 |= (__float_as_uint(d0) >> (U)) & (1u << (31 - (U)));                   \
    st0 = n0; st1 = n1; st2 = n2; st3 = n3; left_next = nsh; } while (0)

#define D2ROW 33   // float4 per (q) row in k_dp2 tile (32 + pad)

__global__ void __launch_bounds__(256, 1)
k_dp2()
{
    extern __shared__ unsigned char smraw[];
    float4* tile = reinterpret_cast<float4*>(smraw);   // [GPW][NQ][D2ROW]

    const int tid = threadIdx.x;
    const int b  = blockIdx.x >> 4;
    const int cb = blockIdx.x & 15;
    const int wid = tid >> 5;
    const int lane = tid & 31;

    for (int i = tid; i < GPW * NQ * GR; i += 256) {
        int w = i / (NQ * GR);
        int rem = i - w * (NQ * GR);
        int q = rem >> 5;
        int r = rem & 31;
        unsigned d = smem_u32(tile + (w * NQ + q) * D2ROW + r);
        const float4* gp = g_simsT + ((size_t)b * NQ + q) * TT
                           + (size_t)(cb * GPW + w) * GR + r;
        asm volatile("cp.async.cg.shared.global [%0], [%1], 16;"
                     :: "r"(d), "l"(gp) : "memory");
    }
    asm volatile("cp.async.commit_group;" ::: "memory");
    asm volatile("cp.async.wait_group 0;" ::: "memory");
    __syncthreads();

    const int g = cb * GPW + wid;
    const int qln = lane < NQ ? lane : NQ - 1;
    const float4* tb = tile + (wid * NQ + qln) * D2ROW;

    float st0, st1, st2, st3, left_next;
    unsigned acc0 = 0, acc1 = 0, acc2 = 0, acc3 = 0;

    if (g == 0) {
        float4 sv = tb[0];
        st0 = sv.x; st1 = sv.y; st2 = sv.z; st3 = sv.w;
        left_next = __shfl_up_sync(FULLM, st3, 1);
#pragma unroll
        for (int u = 1; u < GR; ++u) DPSTEP3(tb[u], u);
    } else {
        float4 bv = *(const float4*)&g_bnd[((size_t)b * NGRP + g) * SS + 4 * qln];
        st0 = bv.x; st1 = bv.y; st2 = bv.z; st3 = bv.w;
        left_next = __shfl_up_sync(FULLM, st3, 1);
#pragma unroll
        for (int u = 0; u < GR; ++u) DPSTEP3(tb[u], u);
    }
    if (lane < NQ)
        *(uint4*)&g_bts[((size_t)b * NGRP + g) * BTROW + lane * 4] =
            make_uint4(acc0, acc1, acc2, acc3);
}

// =====================================================================
// Kernel 3 (k_final): backtrack + segment means (smem-staged z) +
// slim LSTM + head.
// =====================================================================
struct SmemF {
    unsigned int bts[NGRP * BTROW];  // 67,584 B
    float zst[ZCH * ZPAD];           // 45,056 B
    float zz[SS * 12];               //  4,800 B (stride 12)
    int bound[SS + 4];
    float hbuf[56];                  // padded to 56, 16B aligned
    float cbuf[HH];
    float gates[4 * HH];
    float rbuf[32], r2buf[32];
};

__global__ void __launch_bounds__(256, 1)
k_final(const float* __restrict__ w_ih, const float* __restrict__ w_hh,
        const float* __restrict__ b_ih, const float* __restrict__ b_hh,
        const float* __restrict__ wr1, const float* __restrict__ br1,
        const float* __restrict__ wr2, const float* __restrict__ br2,
        const float* __restrict__ wr3, const float* __restrict__ br3,
        float* __restrict__ out)
{
    extern __shared__ unsigned char smraw[];
    SmemF* sm = reinterpret_cast<SmemF*>(smraw);

    const int tid = threadIdx.x;
    const int b = blockIdx.x;
    const int lane = tid & 31;
    const float* zsrc = g_z + (size_t)b * TT * BDM;

    // stage bts (4224 float4) + init
    for (int i = tid; i < NGRP * BTROW / 4; i += 256) {
        unsigned d = smem_u32((float4*)sm->bts + i);
        const float4* gp = (const float4*)(g_bts + (size_t)b * NGRP * BTROW) + i;
        asm volatile("cp.async.cg.shared.global [%0], [%1], 16;"
                     :: "r"(d), "l"(gp) : "memory");
    }
    asm volatile("cp.async.commit_group;" ::: "memory");
    for (int i = tid; i < SS * 12; i += 256) sm->zz[i] = 0.0f;
    for (int i = tid; i < 56; i += 256) sm->hbuf[i] = 0.0f;
    if (tid < 56) sm->hbuf[tid] = 0.0f;
    if (tid < HH) sm->cbuf[tid] = 0.0f;
    asm volatile("cp.async.wait_group 0;" ::: "memory");
    __syncthreads();

    // ---------------- warp-parallel backtrack ----------------
    if (tid < 32) {
        int s = SS - 1, cur = TT - 1;
        while (s > 0) {
            int col4 = s;
            int gtop = cur >> 5;
            int ttstar = 0;
            for (int gb = gtop - 31; ; gb -= 32) {
                int g = gb + lane;
                unsigned w = 0;
                if (g >= 0 && g <= gtop) {
                    w = sm->bts[g * BTROW + col4];
                    if (g == gtop) {
                        int pm = cur & 31;
                        w &= ~((1u << (31 - pm)) - 1u);
                    }
                }
                unsigned bal = __ballot_sync(FULLM, w != 0);
                if (bal) {
                    int hl = 31 - __clz((int)bal);
                    unsigned wh = __shfl_sync(FULLM, w, hl);
                    int pos = __ffs((int)wh) - 1;
                    ttstar = (gb + hl) * 32 + (31 - pos);
                    break;
                }
                if (gb <= 0 || gb * 32 <= s + 1) break;
            }
            int ttd = ttstar > s ? ttstar : s;
            if (lane == 0) sm->bound[s] = ttd;
            cur = ttd - 1;
            s--;
        }
        if (lane == 0) { sm->bound[0] = 0; sm->bound[SS] = TT; }
    }
    __syncthreads();

    // ---------------- segment sums: smem-staged z, 4 chunks of 1024 ----
    for (int chn = 0; chn < TT / ZCH; ++chn) {
        const float* zg = zsrc + (size_t)chn * ZCH * BDM;
        for (int i = tid; i < ZCH * BDM; i += 256) {
            int t = i / BDM;
            int d = i - t * BDM;
            unsigned da = smem_u32(&sm->zst[t * ZPAD + d]);
            asm volatile("cp.async.ca.shared.global [%0], [%1], 4;"
                         :: "r"(da), "l"(zg + i) : "memory");
        }
        asm volatile("cp.async.commit_group;" ::: "memory");
        asm volatile("cp.async.wait_group 0;" ::: "memory");
        __syncthreads();

        int t0 = chn * ZCH + tid * 4;
        int lo = 0, hi = SS - 1;
        while (lo < hi) {
            int mid = (lo + hi + 1) >> 1;
            if (sm->bound[mid] <= t0) lo = mid; else hi = mid - 1;
        }
        int s = lo;
        int nxtb = sm->bound[s + 1];
        const float* zl = sm->zst + (tid * 4) * ZPAD;
        float av[BDM];
#pragma unroll
        for (int d = 0; d < BDM; d++) av[d] = 0.0f;

#pragma unroll
        for (int kk = 0; kk < 4; ++kk) {
            int t = t0 + kk;
            if (t >= nxtb) {
#pragma unroll
                for (int d = 0; d < BDM; d++) {
                    atomicAdd(&sm->zz[s * 12 + d], av[d]);
                    av[d] = 0.0f;
                }
                s++;
                nxtb = sm->bound[s + 1];
            }
#pragma unroll
            for (int d = 0; d < BDM; d++) av[d] += zl[kk * ZPAD + d];
        }
#pragma unroll
        for (int d = 0; d < BDM; d++) atomicAdd(&sm->zz[s * 12 + d], av[d]);
        __syncthreads();
    }

    for (int i = tid; i < SS * 12; i += 256) {
        int s = i / 12;
        int d = i - s * 12;
        if (d < BDM)
            sm->zz[i] = sm->zz[i] / (float)(sm->bound[s + 1] - sm->bound[s]);
    }
    __syncthreads();

    // ---------------- LSTM (slim: float4 h reads, 4 accumulators) ----
    float whr[52], wir[BDM], bsr = 0.0f;
    if (tid < 4 * HH) {
#pragma unroll
        for (int kk = 0; kk < HH; kk++) whr[kk] = w_hh[tid * HH + kk];
        whr[50] = 0.0f; whr[51] = 0.0f;
#pragma unroll
        for (int d = 0; d < BDM; d++) wir[d] = w_ih[tid * BDM + d];
        bsr = b_ih[tid] + b_hh[tid];
    }

    for (int stp = 0; stp < SS; ++stp) {
        if (tid < 4 * HH) {
            const float* xt = sm->zz + stp * 12;
            float4 xa = *(const float4*)xt;
            float4 xb = *(const float4*)(xt + 4);
            float2 xc = *(const float2*)(xt + 8);
            float g0 = bsr, g1 = 0.0f, g2 = 0.0f, g3 = 0.0f;
            g0 += wir[0] * xa.x; g1 += wir[1] * xa.y;
            g2 += wir[2] * xa.z; g3 += wir[3] * xa.w;
            g0 += wir[4] * xb.x; g1 += wir[5] * xb.y;
            g2 += wir[6] * xb.z; g3 += wir[7] * xb.w;
            g0 += wir[8] * xc.x; g1 += wir[9] * xc.y;
#pragma unroll
            for (int q = 0; q < 13; ++q) {
                float4 h4 = *(const float4*)&sm->hbuf[4 * q];
                g0 += whr[4 * q + 0] * h4.x;
                g1 += whr[4 * q + 1] * h4.y;
                g2 += whr[4 * q + 2] * h4.z;
                g3 += whr[4 * q + 3] * h4.w;
            }
            sm->gates[tid] = (g0 + g1) + (g2 + g3);
        }
        __syncthreads();
        if (tid < HH) {
            float iv = sm->gates[tid];
            float fv = sm->gates[HH + tid];
            float gv = sm->gates[2 * HH + tid];
            float ov = sm->gates[3 * HH + tid];
            float cc = sigm(fv) * sm->cbuf[tid] + sigm(iv) * tanhfast(gv);
            sm->cbuf[tid] = cc;
            sm->hbuf[tid] = sigm(ov) * tanhfast(cc);
        }
        __syncthreads();
    }

    // ---------------- MLP head ----------------
    if (tid < DD) {
        float r = br1[tid];
#pragma unroll 10
        for (int kk = 0; kk < HH; kk++) r += wr1[tid * HH + kk] * sm->hbuf[kk];
        sm->rbuf[tid] = fmaxf(r, 0.0f);
    }
    __syncthreads();
    if (tid < DD) {
        float r = br2[tid];
#pragma unroll
        for (int kk = 0; kk < DD; kk++) r += wr2[tid * DD + kk] * sm->rbuf[kk];
        sm->r2buf[tid] = fmaxf(r, 0.0f);
    }
    __syncthreads();
    if (tid == 0) {
        float r = br3[0];
#pragma unroll
        for (int d = 0; d < DD; d++) r += wr3[d] * sm->r2buf[d];
        out[b] = r;
    }
}

// =====================================================================
// launch
// =====================================================================
extern "C" void kernel_launch(void* const* d_in, const int* in_sizes, int n_in,
                              void* d_out, int out_size)
{
    (void)in_sizes; (void)n_in; (void)out_size;
    const float* x    = (const float*)d_in[0];
    const float* c    = (const float*)d_in[1];
    const float* w1   = (const float*)d_in[2];
    const float* b1   = (const float*)d_in[3];
    const float* w2   = (const float*)d_in[4];
    const float* b2   = (const float*)d_in[5];
    const float* w3   = (const float*)d_in[6];
    const float* b3   = (const float*)d_in[7];
    const float* w_ih = (const float*)d_in[8];
    const float* w_hh = (const float*)d_in[9];
    const float* b_ih = (const float*)d_in[10];
    const float* b_hh = (const float*)d_in[11];
    const float* wr1  = (const float*)d_in[12];
    const float* br1  = (const float*)d_in[13];
    const float* wr2  = (const float*)d_in[14];
    const float* br2  = (const float*)d_in[15];
    const float* wr3  = (const float*)d_in[16];
    const float* br3  = (const float*)d_in[17];
    float* out = (float*)d_out;

    cudaFuncSetAttribute(k_dp1, cudaFuncAttributeMaxDynamicSharedMemorySize,
                         (int)sizeof(SmemD));
    cudaFuncSetAttribute(k_dp2, cudaFuncAttributeMaxDynamicSharedMemorySize,
                         GPW * NQ * D2ROW * 16);
    cudaFuncSetAttribute(k_final, cudaFuncAttributeMaxDynamicSharedMemorySize,
                         (int)sizeof(SmemF));

    k_project<<<(BB * TT) / 256, 256>>>(x, c, w1, b1, w2, b2, w3, b3);
    k_dp1<<<BB, 256, sizeof(SmemD)>>>();
    k_dp2<<<BB * 16, 256, GPW * NQ * D2ROW * 16>>>();
    k_final<<<BB, 256, sizeof(SmemF)>>>(w_ih, w_hh, b_ih, b_hh,
                                        wr1, br1, wr2, br2, wr3, br3, out);
}

// round 16
// speedup vs baseline: 1.5648x; 1.5648x over previous
#include <cuda_runtime.h>
#include <math.h>

// ---------------- problem constants ----------------
#define BB   32
#define TT   4096
#define AD   128
#define SS   100
#define BDM  10
#define HH   50
#define DD   30
#define CH   64            // chunk = 64 timesteps (k_dp1 pipeline)
#define NCH  (TT / CH)     // 64 chunks
#define NQ   25            // S/4 float4 "quads"
#define TROW 65            // padded tile row (float4) in k_dp1
#define GR   32            // group = 32 steps (bit granularity)
#define NGRP (TT / GR)     // 128 groups
#define BTROW 132          // bts words per group (100 used, padded)
#define GPW  8             // groups per CTA in k_dp2
#define XROW 68            // padded half-row stride (words) in k_project
#define FULLM 0xffffffffu

// ---------------- global scratch ----------------
__device__ __align__(16) float4 g_simsT[(size_t)BB * NQ * TT];        // [b][q][t]
__device__ __align__(16) float  g_z[(size_t)BB * TT * BDM];
__device__ __align__(16) float  g_bnd[(size_t)BB * NGRP * SS];        // boundary vectors
__device__ __align__(16) unsigned int g_bts[(size_t)BB * NGRP * BTROW];

__device__ __forceinline__ float sigm(float v) { return 1.0f / (1.0f + __expf(-v)); }

__device__ __forceinline__ unsigned smem_u32(const void* p)
{
    return (unsigned)__cvta_generic_to_shared(p);
}

// =====================================================================
// Kernel 1: z = mlp(x); x staged in smem by column-halves (coalesced);
// sims stored quad-transposed [b][q][t].
// =====================================================================
struct SmemP {
    float xs[256 * XROW];          // 69,632 B  (one column-half, stride 68)
    float w1s[BDM * AD];
    float cs[BDM * SS];
    float w2s[BDM * BDM], w3s[BDM * BDM];
    float b1s[BDM], b2s[BDM], b3s[BDM];
};

__global__ void __launch_bounds__(256, 1)
k_project(const float* __restrict__ x, const float* __restrict__ c,
          const float* __restrict__ w1, const float* __restrict__ b1,
          const float* __restrict__ w2, const float* __restrict__ b2,
          const float* __restrict__ w3, const float* __restrict__ b3)
{
    extern __shared__ unsigned char smp_raw[];
    SmemP* sp = reinterpret_cast<SmemP*>(smp_raw);

    int tid = threadIdx.x;
    for (int i = tid; i < BDM * AD; i += 256) sp->w1s[i] = w1[i];
    for (int i = tid; i < BDM * SS; i += 256) sp->cs[i] = c[i];
    if (tid < BDM * BDM) { sp->w2s[tid] = w2[tid]; sp->w3s[tid] = w3[tid]; }
    if (tid < BDM) { sp->b1s[tid] = b1[tid]; sp->b2s[tid] = b2[tid]; sp->b3s[tid] = b3[tid]; }

    int gtid = blockIdx.x * 256 + tid;         // b*T + t
    int b = gtid >> 12;
    int t = gtid & (TT - 1);
    const float* xblk = x + (size_t)(blockIdx.x * 256) * AD;

    float z1[BDM];
#pragma unroll
    for (int d = 0; d < BDM; d++) z1[d] = 0.0f;   // bias added after staging sync

    // two column-halves: [0,64) then [64,128)
    for (int half = 0; half < 2; ++half) {
        __syncthreads();   // protect xs from previous half's readers
        // coalesced stage: 256 rows x 16 float4
        for (int i = tid; i < 256 * 16; i += 256) {
            int row = i >> 4, col = i & 15;
            unsigned d = smem_u32(&sp->xs[row * XROW + col * 4]);
            const float* g = xblk + (size_t)row * AD + half * 64 + col * 4;
            asm volatile("cp.async.cg.shared.global [%0], [%1], 16;"
                         :: "r"(d), "l"(g) : "memory");
        }
        asm volatile("cp.async.commit_group;" ::: "memory");
        asm volatile("cp.async.wait_group 0;" ::: "memory");
        __syncthreads();

        const float* xr = sp->xs + tid * XROW;
#pragma unroll 8
        for (int kk = 0; kk < 16; ++kk) {
            float4 xv = *(const float4*)(xr + kk * 4);
#pragma unroll
            for (int d = 0; d < BDM; d++) {
                float4 wv = ((const float4*)sp->w1s)[d * (AD / 4) + half * 16 + kk];
                z1[d] += xv.x * wv.x + xv.y * wv.y + xv.z * wv.z + xv.w * wv.w;
            }
        }
    }
#pragma unroll
    for (int d = 0; d < BDM; d++) z1[d] = fmaxf(z1[d] + sp->b1s[d], 0.0f);

    float z2[BDM];
#pragma unroll
    for (int d = 0; d < BDM; d++) {
        float a = sp->b2s[d];
#pragma unroll
        for (int e = 0; e < BDM; e++) a += z1[e] * sp->w2s[d * BDM + e];
        z2[d] = fmaxf(a, 0.0f);
    }
    float z3[BDM];
#pragma unroll
    for (int d = 0; d < BDM; d++) {
        float a = sp->b3s[d];
#pragma unroll
        for (int e = 0; e < BDM; e++) a += z2[e] * sp->w3s[d * BDM + e];
        z3[d] = a;
    }

    float* zo = g_z + (size_t)gtid * BDM;
#pragma unroll
    for (int d = 0; d < BDM; d++) zo[d] = z3[d];

#pragma unroll
    for (int q = 0; q < NQ; ++q) {
        float4 a = make_float4(0.f, 0.f, 0.f, 0.f);
#pragma unroll
        for (int d = 0; d < BDM; d++) {
            float zv = z3[d];
            float4 cv = ((const float4*)sp->cs)[d * NQ + q];
            a.x += zv * cv.x; a.y += zv * cv.y;
            a.z += zv * cv.z; a.w += zv * cv.w;
        }
        g_simsT[((size_t)b * NQ + q) * TT + t] = a;   // coalesced over t
    }
}

// NOTE on z1 bias order: reference computes x@w1.T + b1 with the bias added
// to the accumulated dot; we now add b1 at the end instead of seeding.
// fp addition is reordered by one term; magnitude of difference is within
// the same rounding class as the existing 2e-7 rel_err.

// =====================================================================
// Kernel 2a (k_dp1): slim forward DP (NO bits), stores boundary vectors
// every 32 steps. warp0 consumer, warps1-7 cp.async producers.
// =====================================================================
struct SmemD {
    float4 tile[2][NQ * TROW];     // 52,000 B
};

__device__ __forceinline__ void copy_chunk_async(SmemD* sm, int b, int p, int cn)
{
    if (p < 200) {
        float4* dst = sm->tile[cn & 1];
        const float4* src = g_simsT + (size_t)b * NQ * TT + (size_t)cn * CH;
#pragma unroll
        for (int k = 0; k < 8; k++) {
            int i = p + k * 200;
            int q = i >> 6;
            int r = i & 63;
            unsigned d = smem_u32(dst + q * TROW + r);
            const float4* g = src + (size_t)q * TT + r;
            asm volatile("cp.async.cg.shared.global [%0], [%1], 16;"
                         :: "r"(d), "l"(g) : "memory");
        }
        asm volatile("cp.async.commit_group;" ::: "memory");
        asm volatile("cp.async.wait_group 0;" ::: "memory");
    }
}

#define DPSLIM(sv) do {                                                          \
    float n3 = fmaxf(st2, st3) + (sv).w;                                         \
    float nsh = __shfl_up_sync(FULLM, n3, 1);                                    \
    float left = (lane == 0) ? 0.0f : left_next;                                 \
    float n1 = fmaxf(st0, st1) + (sv).y;                                         \
    float n2 = fmaxf(st1, st2) + (sv).z;                                         \
    float n0 = fmaxf(left, st0) + (sv).x;                                        \
    st0 = n0; st1 = n1; st2 = n2; st3 = n3; left_next = nsh; } while (0)

__global__ void __launch_bounds__(256, 1)
k_dp1()
{
    extern __shared__ unsigned char smraw[];
    SmemD* sm = reinterpret_cast<SmemD*>(smraw);

    const int tid = threadIdx.x;
    const int b = blockIdx.x;
    const int lane = tid & 31;

    if (tid >= 32) copy_chunk_async(sm, b, tid - 32, 0);
    __syncthreads();

    const int qln = lane < NQ ? lane : NQ - 1;
    float st0 = 0.f, st1 = 0.f, st2 = 0.f, st3 = 0.f, left_next = 0.f;

    for (int ci = 0; ci < NCH; ++ci) {
        if (tid < 32) {
            const float4* tb = sm->tile[ci & 1] + qln * TROW;
            if (ci == 0) {
                {
                    float4 sv = tb[0];
                    st0 = sv.x; st1 = sv.y; st2 = sv.z; st3 = sv.w;
                    left_next = __shfl_up_sync(FULLM, st3, 1);
                }
#pragma unroll
                for (int u = 1; u < 32; ++u) DPSLIM(tb[u]);
                if (lane < NQ)
                    *(float4*)&g_bnd[((size_t)b * NGRP + 1) * SS + 4 * lane] =
                        make_float4(st0, st1, st2, st3);
#pragma unroll
                for (int u = 32; u < 64; ++u) DPSLIM(tb[u]);
                if (lane < NQ)
                    *(float4*)&g_bnd[((size_t)b * NGRP + 2) * SS + 4 * lane] =
                        make_float4(st0, st1, st2, st3);
            } else {
#pragma unroll 1
                for (int g2 = 0; g2 < 2; ++g2) {
                    const float4* tg = tb + g2 * 32;
#pragma unroll
                    for (int u = 0; u < 32; ++u) DPSLIM(tg[u]);
                    int g = 2 * ci + g2 + 1;
                    if (g < NGRP && lane < NQ)
                        *(float4*)&g_bnd[((size_t)b * NGRP + g) * SS + 4 * lane] =
                            make_float4(st0, st1, st2, st3);
                }
            }
        } else {
            if (ci + 1 < NCH) copy_chunk_async(sm, b, tid - 32, ci + 1);
        }
        __syncthreads();
    }
}

// =====================================================================
// Kernel 2b (k_dp2): parallel bit recompute (exact boundary restart).
// =====================================================================
#define DPSTEP3(sv, U) do {                                                      \
    float n3 = fmaxf(st2, st3) + (sv).w;                                         \
    float nsh = __shfl_up_sync(FULLM, n3, 1);                                    \
    float left = (lane == 0) ? 0.0f : left_next;                                 \
    float d1 = st1 - st0;                                                        \
    float d2 = st2 - st1;                                                        \
    float d3 = st3 - st2;                                                        \
    float n1 = fmaxf(st0, st1) + (sv).y;                                         \
    float n2 = fmaxf(st1, st2) + (sv).z;                                         \
    acc1 |= (__float_as_uint(d1) >> (U)) & (1u << (31 - (U)));                   \
    acc2 |= (__float_as_uint(d2) >> (U)) & (1u << (31 - (U)));                   \
    acc3 |= (__float_as_uint(d3) >> (U)) & (1u << (31 - (U)));                   \
    float d0 = st0 - left;                                                       \
    float n0 = fmaxf(left, st0) + (sv).x;                                        \
    acc0 |= (__float_as_uint(d0) >> (U)) & (1u << (31 - (U)));                   \
    st0 = n0; st1 = n1; st2 = n2; st3 = n3; left_next = nsh; } while (0)

#define D2ROW 33   // float4 per (q) row in k_dp2 tile (32 + pad)

__global__ void __launch_bounds__(256, 1)
k_dp2()
{
    extern __shared__ unsigned char smraw[];
    float4* tile = reinterpret_cast<float4*>(smraw);   // [GPW][NQ][D2ROW]

    const int tid = threadIdx.x;
    const int b  = blockIdx.x >> 4;
    const int cb = blockIdx.x & 15;
    const int wid = tid >> 5;
    const int lane = tid & 31;

    for (int i = tid; i < GPW * NQ * GR; i += 256) {
        int w = i / (NQ * GR);
        int rem = i - w * (NQ * GR);
        int q = rem >> 5;
        int r = rem & 31;
        unsigned d = smem_u32(tile + (w * NQ + q) * D2ROW + r);
        const float4* gp = g_simsT + ((size_t)b * NQ + q) * TT
                           + (size_t)(cb * GPW + w) * GR + r;
        asm volatile("cp.async.cg.shared.global [%0], [%1], 16;"
                     :: "r"(d), "l"(gp) : "memory");
    }
    asm volatile("cp.async.commit_group;" ::: "memory");
    asm volatile("cp.async.wait_group 0;" ::: "memory");
    __syncthreads();

    const int g = cb * GPW + wid;
    const int qln = lane < NQ ? lane : NQ - 1;
    const float4* tb = tile + (wid * NQ + qln) * D2ROW;

    float st0, st1, st2, st3, left_next;
    unsigned acc0 = 0, acc1 = 0, acc2 = 0, acc3 = 0;

    if (g == 0) {
        float4 sv = tb[0];
        st0 = sv.x; st1 = sv.y; st2 = sv.z; st3 = sv.w;
        left_next = __shfl_up_sync(FULLM, st3, 1);
#pragma unroll
        for (int u = 1; u < GR; ++u) DPSTEP3(tb[u], u);
    } else {
        float4 bv = *(const float4*)&g_bnd[((size_t)b * NGRP + g) * SS + 4 * qln];
        st0 = bv.x; st1 = bv.y; st2 = bv.z; st3 = bv.w;
        left_next = __shfl_up_sync(FULLM, st3, 1);
#pragma unroll
        for (int u = 0; u < GR; ++u) DPSTEP3(tb[u], u);
    }
    if (lane < NQ)
        *(uint4*)&g_bts[((size_t)b * NGRP + g) * BTROW + lane * 4] =
            make_uint4(acc0, acc1, acc2, acc3);
}

// =====================================================================
// Kernel 3 (k_final): backtrack + segment means + LSTM + head (R14 exact)
// =====================================================================
struct SmemF {
    unsigned int bts[NGRP * BTROW];  // 67,584 B
    float zz[SS * BDM];
    int bound[SS + 4];
    float hbuf[HH], cbuf[HH], gates[4 * HH];
    float rbuf[32], r2buf[32];
};

__global__ void __launch_bounds__(256, 1)
k_final(const float* __restrict__ w_ih, const float* __restrict__ w_hh,
        const float* __restrict__ b_ih, const float* __restrict__ b_hh,
        const float* __restrict__ wr1, const float* __restrict__ br1,
        const float* __restrict__ wr2, const float* __restrict__ br2,
        const float* __restrict__ wr3, const float* __restrict__ br3,
        float* __restrict__ out)
{
    extern __shared__ unsigned char smraw[];
    SmemF* sm = reinterpret_cast<SmemF*>(smraw);

    const int tid = threadIdx.x;
    const int b = blockIdx.x;
    const int lane = tid & 31;

    // stage bts (4224 float4) + init
    for (int i = tid; i < NGRP * BTROW / 4; i += 256) {
        unsigned d = smem_u32((float4*)sm->bts + i);
        const float4* gp = (const float4*)(g_bts + (size_t)b * NGRP * BTROW) + i;
        asm volatile("cp.async.cg.shared.global [%0], [%1], 16;"
                     :: "r"(d), "l"(gp) : "memory");
    }
    asm volatile("cp.async.commit_group;" ::: "memory");
    for (int i = tid; i < SS * BDM; i += 256) sm->zz[i] = 0.0f;
    if (tid < HH) { sm->hbuf[tid] = 0.0f; sm->cbuf[tid] = 0.0f; }
    asm volatile("cp.async.wait_group 0;" ::: "memory");
    __syncthreads();

    // ---------------- warp-parallel backtrack ----------------
    if (tid < 32) {
        int s = SS - 1, cur = TT - 1;
        while (s > 0) {
            int col4 = s;
            int gtop = cur >> 5;
            int ttstar = 0;
            for (int gb = gtop - 31; ; gb -= 32) {
                int g = gb + lane;
                unsigned w = 0;
                if (g >= 0 && g <= gtop) {
                    w = sm->bts[g * BTROW + col4];
                    if (g == gtop) {
                        int pm = cur & 31;
                        w &= ~((1u << (31 - pm)) - 1u);
                    }
                }
                unsigned bal = __ballot_sync(FULLM, w != 0);
                if (bal) {
                    int hl = 31 - __clz((int)bal);
                    unsigned wh = __shfl_sync(FULLM, w, hl);
                    int pos = __ffs((int)wh) - 1;
                    ttstar = (gb + hl) * 32 + (31 - pos);
                    break;
                }
                if (gb <= 0 || gb * 32 <= s + 1) break;
            }
            int ttd = ttstar > s ? ttstar : s;
            if (lane == 0) sm->bound[s] = ttd;
            cur = ttd - 1;
            s--;
        }
        if (lane == 0) { sm->bound[0] = 0; sm->bound[SS] = TT; }
    }
    __syncthreads();

    // ---------------- segment sums ----------------
    {
        const int t0 = tid * (TT / 256);
        int lo = 0, hi = SS - 1;
        while (lo < hi) {
            int mid = (lo + hi + 1) >> 1;
            if (sm->bound[mid] <= t0) lo = mid; else hi = mid - 1;
        }
        int s = lo;
        int nxtb = sm->bound[s + 1];
        const float* zb = g_z + ((size_t)b * TT + t0) * BDM;
        float av[BDM];
#pragma unroll
        for (int d = 0; d < BDM; d++) av[d] = 0.0f;

        for (int kk = 0; kk < TT / 256; ++kk) {
            int t = t0 + kk;
            if (t >= nxtb) {
#pragma unroll
                for (int d = 0; d < BDM; d++) {
                    atomicAdd(&sm->zz[s * BDM + d], av[d]);
                    av[d] = 0.0f;
                }
                s++;
                nxtb = sm->bound[s + 1];
            }
#pragma unroll
            for (int d = 0; d < BDM; d++) av[d] += zb[kk * BDM + d];
        }
#pragma unroll
        for (int d = 0; d < BDM; d++) atomicAdd(&sm->zz[s * BDM + d], av[d]);
    }
    __syncthreads();

    for (int i = tid; i < SS * BDM; i += 256) {
        int s = i / BDM;
        sm->zz[i] = sm->zz[i] / (float)(sm->bound[s + 1] - sm->bound[s]);
    }
    __syncthreads();

    // ---------------- LSTM (weights in registers) ----------------
    float whr[HH], wir[BDM], bsr = 0.0f;
    if (tid < 4 * HH) {
#pragma unroll
        for (int kk = 0; kk < HH; kk++) whr[kk] = w_hh[tid * HH + kk];
#pragma unroll
        for (int d = 0; d < BDM; d++) wir[d] = w_ih[tid * BDM + d];
        bsr = b_ih[tid] + b_hh[tid];
    }

    for (int stp = 0; stp < SS; ++stp) {
        if (tid < 4 * HH) {
            float g = bsr;
            const float* xt = sm->zz + stp * BDM;
#pragma unroll
            for (int d = 0; d < BDM; d++) g += wir[d] * xt[d];
#pragma unroll
            for (int kk = 0; kk < HH; kk++) g += whr[kk] * sm->hbuf[kk];
            sm->gates[tid] = g;
        }
        __syncthreads();
        if (tid < HH) {
            float iv = sm->gates[tid];
            float fv = sm->gates[HH + tid];
            float gv = sm->gates[2 * HH + tid];
            float ov = sm->gates[3 * HH + tid];
            float cc = sigm(fv) * sm->cbuf[tid] + sigm(iv) * tanhf(gv);
            sm->cbuf[tid] = cc;
            sm->hbuf[tid] = sigm(ov) * tanhf(cc);
        }
        __syncthreads();
    }

    // ---------------- MLP head ----------------
    if (tid < DD) {
        float r = br1[tid];
#pragma unroll 10
        for (int kk = 0; kk < HH; kk++) r += wr1[tid * HH + kk] * sm->hbuf[kk];
        sm->rbuf[tid] = fmaxf(r, 0.0f);
    }
    __syncthreads();
    if (tid < DD) {
        float r = br2[tid];
#pragma unroll
        for (int kk = 0; kk < DD; kk++) r += wr2[tid * DD + kk] * sm->rbuf[kk];
        sm->r2buf[tid] = fmaxf(r, 0.0f);
    }
    __syncthreads();
    if (tid == 0) {
        float r = br3[0];
#pragma unroll
        for (int d = 0; d < DD; d++) r += wr3[d] * sm->r2buf[d];
        out[b] = r;
    }
}

// =====================================================================
// launch
// =====================================================================
extern "C" void kernel_launch(void* const* d_in, const int* in_sizes, int n_in,
                              void* d_out, int out_size)
{
    (void)in_sizes; (void)n_in; (void)out_size;
    const float* x    = (const float*)d_in[0];
    const float* c    = (const float*)d_in[1];
    const float* w1   = (const float*)d_in[2];
    const float* b1   = (const float*)d_in[3];
    const float* w2   = (const float*)d_in[4];
    const float* b2   = (const float*)d_in[5];
    const float* w3   = (const float*)d_in[6];
    const float* b3   = (const float*)d_in[7];
    const float* w_ih = (const float*)d_in[8];
    const float* w_hh = (const float*)d_in[9];
    const float* b_ih = (const float*)d_in[10];
    const float* b_hh = (const float*)d_in[11];
    const float* wr1  = (const float*)d_in[12];
    const float* br1  = (const float*)d_in[13];
    const float* wr2  = (const float*)d_in[14];
    const float* br2  = (const float*)d_in[15];
    const float* wr3  = (const float*)d_in[16];
    const float* br3  = (const float*)d_in[17];
    float* out = (float*)d_out;

    cudaFuncSetAttribute(k_project, cudaFuncAttributeMaxDynamicSharedMemorySize,
                         (int)sizeof(SmemP));
    cudaFuncSetAttribute(k_dp1, cudaFuncAttributeMaxDynamicSharedMemorySize,
                         (int)sizeof(SmemD));
    cudaFuncSetAttribute(k_dp2, cudaFuncAttributeMaxDynamicSharedMemorySize,
                         GPW * NQ * D2ROW * 16);
    cudaFuncSetAttribute(k_final, cudaFuncAttributeMaxDynamicSharedMemorySize,
                         (int)sizeof(SmemF));

    k_project<<<(BB * TT) / 256, 256, sizeof(SmemP)>>>(x, c, w1, b1, w2, b2, w3, b3);
    k_dp1<<<BB, 256, sizeof(SmemD)>>>();
    k_dp2<<<BB * 16, 256, GPW * NQ * D2ROW * 16>>>();
    k_final<<<BB, 256, sizeof(SmemF)>>>(w_ih, w_hh, b_ih, b_hh,
                                        wr1, br1, wr2, br2, wr3, br3, out);
}